// round 17
// baseline (speedup 1.0000x reference)
#include <cuda_runtime.h>
#include <cuda_fp16.h>
#include <cstdint>
#include <cstddef>

// ---------------- problem constants ----------------
#define E_LOC   8
#define B_DIM   4
#define C_CAP   1024
#define D_MODEL 1024
#define D_FF    4096

// ---------------- tile config ----------------
// fp16 HMMA m16n8k16, fp32 accum. Block 256(M) x 128(N) x 32(K), 256 threads =
// 8 warps (4M x 2N), warp tile 64x64. Bigger M-tile cuts L2->SMEM traffic per
// MAC by 25% (the round-16 binder). ldmatrix feed, 4-stage cp.async, 1 CTA/SM.
#define BM 256
#define BN 128
#define BK 32
#define STAGES 4
#define THREADS 256

#define PAD_LD      40                      // halves per row (80B): LDSM conflict-free
#define A_HALVES    (BM * PAD_LD)           // 10240
#define B_HALVES    (BN * PAD_LD)           // 5120
#define STG_HALVES  (A_HALVES + B_HALVES)   // 15360
#define STG_BYTES   (STG_HALVES * 2)        // 30720
#define SMEM_BYTES  (STAGES * STG_BYTES)    // 122880

// ---------------- scratch (static __device__: no runtime alloc) ----------------
__device__ __half g_hid[(size_t)B_DIM * E_LOC * C_CAP * D_FF];     // 256 MB
__device__ __half g_xh [(size_t)B_DIM * E_LOC * C_CAP * D_MODEL];  // 64 MB
__device__ __half g_w1h[(size_t)E_LOC * D_FF * D_MODEL];           // 64 MB
__device__ __half g_w2h[(size_t)E_LOC * D_MODEL * D_FF];           // 64 MB

// ---------------- helpers ----------------
__device__ __forceinline__ uint32_t smem_u32(const void* p) {
    uint32_t a;
    asm("{ .reg .u64 t; cvta.to.shared.u64 t, %1; cvt.u32.u64 %0, t; }" : "=r"(a) : "l"(p));
    return a;
}
__device__ __forceinline__ void cp_async16(uint32_t saddr, const void* g) {
    asm volatile("cp.async.cg.shared.global [%0], [%1], 16;" :: "r"(saddr), "l"(g));
}
#define CP_COMMIT() asm volatile("cp.async.commit_group;" ::: "memory")
#define CP_WAIT2()  asm volatile("cp.async.wait_group 2;" ::: "memory")

__device__ __forceinline__ void ldsm_x4(uint32_t* r, uint32_t addr) {
    asm volatile("ldmatrix.sync.aligned.m8n8.x4.shared.b16 {%0,%1,%2,%3}, [%4];"
                 : "=r"(r[0]), "=r"(r[1]), "=r"(r[2]), "=r"(r[3]) : "r"(addr));
}
__device__ __forceinline__ float gelu_exact(float x) {
    return 0.5f * x * (1.0f + erff(x * 0.7071067811865476f));
}
__device__ __forceinline__ uint32_t h2_to_u32(__half2 h) {
    return *reinterpret_cast<uint32_t*>(&h);
}

// ---------------- stage loader: gmem(half) -> padded smem via cp.async ----------------
// A: 256 rows x 4 chunks = 1024 / 256 thr = 4 each; B: 128 rows x 4 = 512 / 256 = 2 each.
__device__ __forceinline__ void load_stage(uint32_t sbase, int buf, int kt,
                                           const __half* __restrict__ Ab,
                                           const __half* __restrict__ Bb,
                                           int K, int tid)
{
    const int k0 = kt * BK;
    const uint32_t abase = sbase + (uint32_t)buf * STG_BYTES;
    const uint32_t bbase = abase + A_HALVES * 2;
    const int r0 = tid >> 2, j = tid & 3;           // base row, chunk
#pragma unroll
    for (int i = 0; i < 4; i++) {
        int r = r0 + i * 64;                        // rows 0..255
        cp_async16(abase + r * (PAD_LD * 2) + j * 16, Ab + (size_t)r * K + k0 + j * 8);
    }
#pragma unroll
    for (int i = 0; i < 2; i++) {
        int r = r0 + i * 64;                        // rows 0..127
        cp_async16(bbase + r * (PAD_LD * 2) + j * 16, Bb + (size_t)r * K + k0 + j * 8);
    }
}

// ---------------- grouped NT GEMM: C = A @ B^T (+bias)(+GELU) -----------------
// GELU=true writes __half hidden; GELU=false writes float.
template <bool GELU>
__global__ __launch_bounds__(THREADS, 1)
void gemm_nt_f16(const __half* __restrict__ A, const __half* __restrict__ Bw,
                 const float* __restrict__ bias, void* __restrict__ Cv,
                 int K, int ldc, size_t a_zstr, size_t b_estr, int bias_n, size_t c_zstr)
{
    extern __shared__ __half smem[];

    const int tid  = threadIdx.x;
    const int lane = tid & 31;
    const int warp = tid >> 5;
    const int wm   = warp & 3;    // rows wm*64 (0..3)
    const int wn   = warp >> 2;   // cols wn*64 (0..1)

    const int z = blockIdx.z;
    const int e = z & (E_LOC - 1);

    const __half* Ab   = A    + (size_t)z * a_zstr + (size_t)blockIdx.y * BM * K;
    const __half* Bb   = Bw   + (size_t)e * b_estr + (size_t)blockIdx.x * BN * K;
    const float* biasb = bias + (size_t)e * bias_n + (size_t)blockIdx.x * BN;
    const size_t cbase = (size_t)z * c_zstr + (size_t)blockIdx.y * BM * ldc
                       + (size_t)blockIdx.x * BN;

    const uint32_t sb = smem_u32(smem);

    // ldmatrix lane addresses (byte offsets within a stage).
    const int grp = lane >> 3;
    // A x4 per (mt,ks): rows [wm*64+mt*16, +16) x k16
    const uint32_t a_lane = ((uint32_t)(wm * 64 + (grp & 1) * 8 + (lane & 7)) * PAD_LD
                             + (grp >> 1) * 8) * 2;
    // B x4 per (p,ks): cols [wn*64+p*16, +16) x k16   (p = nt pair)
    const uint32_t b_lane = ((uint32_t)(wn * 64 + (grp >> 1) * 8 + (lane & 7)) * PAD_LD
                             + (grp & 1) * 8) * 2;

    float acc[4][8][4];
#pragma unroll
    for (int mt = 0; mt < 4; mt++)
#pragma unroll
        for (int nt = 0; nt < 8; nt++)
#pragma unroll
            for (int i = 0; i < 4; i++) acc[mt][nt][i] = 0.0f;

    const int NK = K >> 5;

    load_stage(sb, 0, 0, Ab, Bb, K, tid); CP_COMMIT();
    load_stage(sb, 1, 1, Ab, Bb, K, tid); CP_COMMIT();
    load_stage(sb, 2, 2, Ab, Bb, K, tid); CP_COMMIT();

#pragma unroll 1
    for (int kt = 0; kt < NK; ++kt) {
        CP_WAIT2();                 // stage kt resident
        __syncthreads();            // all warps done reading buffer being refilled

        if (kt + 3 < NK)
            load_stage(sb, (kt + 3) & 3, kt + 3, Ab, Bb, K, tid);
        CP_COMMIT();                // empty commit keeps group accounting uniform

        const uint32_t abase = sb + (uint32_t)(kt & 3) * STG_BYTES;
        const uint32_t bbase = abase + A_HALVES * 2;

#pragma unroll
        for (int ks = 0; ks < 2; ks++) {        // two K=16 steps per 32-K tile
            uint32_t af[4][4], bf[4][4];
#pragma unroll
            for (int mt = 0; mt < 4; mt++)
                ldsm_x4(af[mt], abase + a_lane + mt * (16 * PAD_LD * 2) + ks * 32);
#pragma unroll
            for (int p = 0; p < 4; p++)
                ldsm_x4(bf[p], bbase + b_lane + p * (16 * PAD_LD * 2) + ks * 32);

#pragma unroll
            for (int mt = 0; mt < 4; mt++)
#pragma unroll
                for (int nt = 0; nt < 8; nt++) {
                    const uint32_t b0 = bf[nt >> 1][(nt & 1) * 2 + 0];
                    const uint32_t b1 = bf[nt >> 1][(nt & 1) * 2 + 1];
                    asm volatile(
                        "mma.sync.aligned.m16n8k16.row.col.f32.f16.f16.f32 "
                        "{%0,%1,%2,%3},{%4,%5,%6,%7},{%8,%9},{%0,%1,%2,%3};"
                        : "+f"(acc[mt][nt][0]), "+f"(acc[mt][nt][1]),
                          "+f"(acc[mt][nt][2]), "+f"(acc[mt][nt][3])
                        : "r"(af[mt][0]), "r"(af[mt][1]), "r"(af[mt][2]), "r"(af[mt][3]),
                          "r"(b0), "r"(b1));
                }
        }
    }

    // ---------------- epilogue ----------------
#pragma unroll
    for (int mt = 0; mt < 4; mt++) {
        const int r0 = wm * 64 + mt * 16 + (lane >> 2);
#pragma unroll
        for (int nt = 0; nt < 8; nt++) {
            const int c0 = wn * 64 + nt * 8 + 2 * (lane & 3);
            const float b0 = biasb[c0];
            const float b1 = biasb[c0 + 1];
            float v0 = acc[mt][nt][0] + b0;
            float v1 = acc[mt][nt][1] + b1;
            float v2 = acc[mt][nt][2] + b0;
            float v3 = acc[mt][nt][3] + b1;
            if (GELU) {
                __half* Ch = (__half*)Cv + cbase;
                __half2 p0 = __floats2half2_rn(gelu_exact(v0), gelu_exact(v1));
                __half2 p1 = __floats2half2_rn(gelu_exact(v2), gelu_exact(v3));
                *reinterpret_cast<__half2*>(Ch + (size_t)r0 * ldc + c0)       = p0;
                *reinterpret_cast<__half2*>(Ch + (size_t)(r0 + 8) * ldc + c0) = p1;
            } else {
                float* Cf = (float*)Cv + cbase;
                *reinterpret_cast<float2*>(Cf + (size_t)r0 * ldc + c0)       = make_float2(v0, v1);
                *reinterpret_cast<float2*>(Cf + (size_t)(r0 + 8) * ldc + c0) = make_float2(v2, v3);
            }
        }
    }
}

// ---------------- prepass: fp32 -> fp16 (rn) ----------------
__global__ void f2h_kernel(const float4* __restrict__ in, uint4* __restrict__ out, size_t n8)
{
    size_t i = (size_t)blockIdx.x * blockDim.x + threadIdx.x;
    const size_t stride = (size_t)gridDim.x * blockDim.x;
    for (; i < n8; i += stride) {
        float4 a = in[2 * i];
        float4 b = in[2 * i + 1];
        uint4 o;
        o.x = h2_to_u32(__floats2half2_rn(a.x, a.y));
        o.y = h2_to_u32(__floats2half2_rn(a.z, a.w));
        o.z = h2_to_u32(__floats2half2_rn(b.x, b.y));
        o.w = h2_to_u32(__floats2half2_rn(b.z, b.w));
        out[i] = o;
    }
}

// ---------------- launch ----------------
extern "C" void kernel_launch(void* const* d_in, const int* in_sizes, int n_in,
                              void* d_out, int out_size)
{
    const float* x  = (const float*)d_in[0];  // [B, E*C, D]
    const float* w1 = (const float*)d_in[1];  // [E, F, D]
    const float* b1 = (const float*)d_in[2];  // [E, F]
    const float* w2 = (const float*)d_in[3];  // [E, D, F]
    const float* b2 = (const float*)d_in[4];  // [E, D]
    float* out = (float*)d_out;               // [B, E*C, D]

    __half *hid, *xh, *w1h, *w2h;
    cudaGetSymbolAddress((void**)&hid, g_hid);
    cudaGetSymbolAddress((void**)&xh,  g_xh);
    cudaGetSymbolAddress((void**)&w1h, g_w1h);
    cudaGetSymbolAddress((void**)&w2h, g_w2h);

    cudaFuncSetAttribute(gemm_nt_f16<true>,  cudaFuncAttributeMaxDynamicSharedMemorySize, SMEM_BYTES);
    cudaFuncSetAttribute(gemm_nt_f16<false>, cudaFuncAttributeMaxDynamicSharedMemorySize, SMEM_BYTES);

    const size_t nx = (size_t)B_DIM * E_LOC * C_CAP * D_MODEL;  // 32M
    const size_t nw = (size_t)E_LOC * D_FF * D_MODEL;           // 32M
    f2h_kernel<<<2048, 256>>>((const float4*)x,  (uint4*)xh,  nx / 8);
    f2h_kernel<<<2048, 256>>>((const float4*)w1, (uint4*)w1h, nw / 8);
    f2h_kernel<<<2048, 256>>>((const float4*)w2, (uint4*)w2h, nw / 8);

    const int ZB = B_DIM * E_LOC;  // 32

    // GEMM1: hid = half(gelu(x @ w1^T + b1))   M=1024, N=4096, K=1024
    {
        dim3 grid(D_FF / BN, C_CAP / BM, ZB);   // (32, 4, 32)
        gemm_nt_f16<true><<<grid, THREADS, SMEM_BYTES>>>(
            xh, w1h, b1, hid,
            /*K=*/D_MODEL, /*ldc=*/D_FF,
            /*a_zstr=*/(size_t)C_CAP * D_MODEL,
            /*b_estr=*/(size_t)D_FF * D_MODEL,
            /*bias_n=*/D_FF,
            /*c_zstr=*/(size_t)C_CAP * D_FF);
    }

    // GEMM2: out = hid @ w2^T + b2             M=1024, N=1024, K=4096
    {
        dim3 grid(D_MODEL / BN, C_CAP / BM, ZB);  // (8, 4, 32)
        gemm_nt_f16<false><<<grid, THREADS, SMEM_BYTES>>>(
            hid, w2h, b2, out,
            /*K=*/D_FF, /*ldc=*/D_MODEL,
            /*a_zstr=*/(size_t)C_CAP * D_FF,
            /*b_estr=*/(size_t)D_MODEL * D_FF,
            /*bias_n=*/D_MODEL,
            /*c_zstr=*/(size_t)C_CAP * D_MODEL);
    }
}